// round 5
// baseline (speedup 1.0000x reference)
#include <cuda_runtime.h>

// DistMult edge scoring: out[e] = sum_d X[src[e],d] * R[rel[e],d] * X[dst[e],d]
//
// Round 5: keep 4 edges / 16-lane group (7 wf/edge), restore occupancy.
//  - __launch_bounds__(256, 6): cap 42 regs -> 6 blocks/SM (75% occ)
//  - explicit two-wave structure, each wave fully retired (dot + offset-8
//    fold + pack) before the next wave's gathers, to keep float4 liveness
//    at one wave (6 x float4) and avoid spills under the reg cap.
//  - int4 index loads, 8 SHFLs per 4 edges, contiguous scalar stores.

constexpr int XDIM            = 64;
constexpr int LANES           = 16;
constexpr int EDGES_PER_GROUP = 4;
constexpr int BLOCK           = 256;

__device__ __forceinline__ float dot3(float4 a, float4 r, float4 b) {
    return a.x * r.x * b.x
         + a.y * r.y * b.y
         + a.z * r.z * b.z
         + a.w * r.w * b.w;
}

__global__ __launch_bounds__(BLOCK, 6)
void distmult_kernel(const float* __restrict__ X,
                     const float* __restrict__ R,
                     const int*   __restrict__ edge_list,  // [2, E]
                     const int*   __restrict__ edge_type,  // [1, E]
                     float*       __restrict__ out,        // [E]
                     int num_edges)
{
    int gid   = blockIdx.x * BLOCK + threadIdx.x;
    int group = gid >> 4;
    int lane  = gid & (LANES - 1);

    int e0 = group * EDGES_PER_GROUP;

    int4 src, dst, rel;
    if (e0 + 3 < num_edges) {
        // Fast path (always taken when E % 4 == 0): vectorized index loads.
        src = __ldg(reinterpret_cast<const int4*>(edge_list + e0));
        dst = __ldg(reinterpret_cast<const int4*>(edge_list + num_edges + e0));
        rel = __ldg(reinterpret_cast<const int4*>(edge_type + e0));
    } else {
        int c0 = min(e0 + 0, num_edges - 1);
        int c1 = min(e0 + 1, num_edges - 1);
        int c2 = min(e0 + 2, num_edges - 1);
        int c3 = min(e0 + 3, num_edges - 1);
        src = make_int4(__ldg(&edge_list[c0]), __ldg(&edge_list[c1]),
                        __ldg(&edge_list[c2]), __ldg(&edge_list[c3]));
        dst = make_int4(__ldg(&edge_list[num_edges + c0]), __ldg(&edge_list[num_edges + c1]),
                        __ldg(&edge_list[num_edges + c2]), __ldg(&edge_list[num_edges + c3]));
        rel = make_int4(__ldg(&edge_type[c0]), __ldg(&edge_type[c1]),
                        __ldg(&edge_type[c2]), __ldg(&edge_type[c3]));
    }

    const float4* X4 = reinterpret_cast<const float4*>(X);
    const float4* R4 = reinterpret_cast<const float4*>(R);
    const int V4 = XDIM / 4;  // 16 float4 per row

    // ── Wave 1: edges 0,1 — load, dot, fold(8), pack. Fully retired before
    //    wave 2 so only 6 float4 are live at a time.
    float a;
    {
        float4 a0 = __ldg(X4 + src.x * V4 + lane);
        float4 b0 = __ldg(X4 + dst.x * V4 + lane);
        float4 r0 = __ldg(R4 + rel.x * V4 + lane);
        float4 a1 = __ldg(X4 + src.y * V4 + lane);
        float4 b1 = __ldg(X4 + dst.y * V4 + lane);
        float4 r1 = __ldg(R4 + rel.y * V4 + lane);
        float s0 = dot3(a0, r0, b0);
        float s1 = dot3(a1, r1, b1);
        s0 += __shfl_xor_sync(0xFFFFFFFFu, s0, 8);
        s1 += __shfl_xor_sync(0xFFFFFFFFu, s1, 8);
        a = (lane & 8) ? s1 : s0;   // edge0 in lanes 0-7, edge1 in lanes 8-15
    }

    // ── Wave 2: edges 2,3
    float b;
    {
        float4 a2 = __ldg(X4 + src.z * V4 + lane);
        float4 b2 = __ldg(X4 + dst.z * V4 + lane);
        float4 r2 = __ldg(R4 + rel.z * V4 + lane);
        float4 a3 = __ldg(X4 + src.w * V4 + lane);
        float4 b3 = __ldg(X4 + dst.w * V4 + lane);
        float4 r3 = __ldg(R4 + rel.w * V4 + lane);
        float s2 = dot3(a2, r2, b2);
        float s3 = dot3(a3, r3, b3);
        s2 += __shfl_xor_sync(0xFFFFFFFFu, s2, 8);
        s3 += __shfl_xor_sync(0xFFFFFFFFu, s3, 8);
        b = (lane & 8) ? s3 : s2;   // edge2 in lanes 0-7, edge3 in lanes 8-15
    }

    // ── Cross-wave fold: offset 4, pack, then offsets 2, 1.
    a += __shfl_xor_sync(0xFFFFFFFFu, a, 4);
    b += __shfl_xor_sync(0xFFFFFFFFu, b, 4);
    float c = (lane & 4) ? b : a;
    // quads: lanes0-3 -> edge0, 4-7 -> edge2, 8-11 -> edge1, 12-15 -> edge3
    c += __shfl_xor_sync(0xFFFFFFFFu, c, 2);
    c += __shfl_xor_sync(0xFFFFFFFFu, c, 1);

    // lane0 -> e0+0, lane4 -> e0+2, lane8 -> e0+1, lane12 -> e0+3
    if ((lane & 3) == 0) {
        int off = ((lane >> 3) & 1) | (((lane >> 2) & 1) << 1);
        int e = e0 + off;
        if (e < num_edges)
            out[e] = c;
    }
}

extern "C" void kernel_launch(void* const* d_in, const int* in_sizes, int n_in,
                              void* d_out, int out_size)
{
    const float* X  = (const float*)d_in[0];
    const float* R  = (const float*)d_in[1];
    const int* edge_list = (const int*)d_in[2];
    const int* edge_type = (const int*)d_in[3];
    float* out = (float*)d_out;

    int num_edges = in_sizes[3];

    int groups = (num_edges + EDGES_PER_GROUP - 1) / EDGES_PER_GROUP;
    long long total_threads = (long long)groups * LANES;
    int grid = (int)((total_threads + BLOCK - 1) / BLOCK);

    distmult_kernel<<<grid, BLOCK>>>(X, R, edge_list, edge_type, out, num_edges);
}

// round 6
// speedup vs baseline: 1.2083x; 1.2083x over previous
#include <cuda_runtime.h>

// DistMult edge scoring: out[e] = sum_d X[src[e],d] * R[rel[e],d] * X[dst[e],d]
//
// Round 6: round-4 batched-load order (the winner) + occupancy restore.
//  - 4 edges / 16-lane group, int4 index loads, folded 8-SHFL reduction.
//  - 9+3 load batching: gathers for edges 0-2 issued together (MLP=9),
//    edge-0 dot frees 12 regs, then edge-3 gathers, then remaining dots.
//    ALL shuffles strictly after all loads/dots -> no SHFL in load shadow
//    (round 5 post-mortem: that serialization cost 8us).
//  - peak float4 liveness 9 (36 regs) -> fits __launch_bounds__(256, 6)
//    (42-reg cap, 6 blocks/SM, 75% occupancy) without spills.

constexpr int XDIM            = 64;
constexpr int LANES           = 16;
constexpr int EDGES_PER_GROUP = 4;
constexpr int BLOCK           = 256;

__device__ __forceinline__ float dot3(float4 a, float4 r, float4 b) {
    return a.x * r.x * b.x
         + a.y * r.y * b.y
         + a.z * r.z * b.z
         + a.w * r.w * b.w;
}

__global__ __launch_bounds__(BLOCK, 6)
void distmult_kernel(const float* __restrict__ X,
                     const float* __restrict__ R,
                     const int*   __restrict__ edge_list,  // [2, E]
                     const int*   __restrict__ edge_type,  // [1, E]
                     float*       __restrict__ out,        // [E]
                     int num_edges)
{
    int gid   = blockIdx.x * BLOCK + threadIdx.x;
    int group = gid >> 4;
    int lane  = gid & (LANES - 1);

    int e0 = group * EDGES_PER_GROUP;

    int4 src, dst, rel;
    if (e0 + 3 < num_edges) {
        // Fast path (always taken when E % 4 == 0): vectorized index loads.
        src = __ldg(reinterpret_cast<const int4*>(edge_list + e0));
        dst = __ldg(reinterpret_cast<const int4*>(edge_list + num_edges + e0));
        rel = __ldg(reinterpret_cast<const int4*>(edge_type + e0));
    } else {
        int c0 = min(e0 + 0, num_edges - 1);
        int c1 = min(e0 + 1, num_edges - 1);
        int c2 = min(e0 + 2, num_edges - 1);
        int c3 = min(e0 + 3, num_edges - 1);
        src = make_int4(__ldg(&edge_list[c0]), __ldg(&edge_list[c1]),
                        __ldg(&edge_list[c2]), __ldg(&edge_list[c3]));
        dst = make_int4(__ldg(&edge_list[num_edges + c0]), __ldg(&edge_list[num_edges + c1]),
                        __ldg(&edge_list[num_edges + c2]), __ldg(&edge_list[num_edges + c3]));
        rel = make_int4(__ldg(&edge_type[c0]), __ldg(&edge_type[c1]),
                        __ldg(&edge_type[c2]), __ldg(&edge_type[c3]));
    }

    const float4* X4 = reinterpret_cast<const float4*>(X);
    const float4* R4 = reinterpret_cast<const float4*>(R);
    const int V4 = XDIM / 4;  // 16 float4 per row

    // ── Batch 1: 9 gathers in flight (edges 0,1,2).
    float4 a0 = __ldg(X4 + src.x * V4 + lane);
    float4 b0 = __ldg(X4 + dst.x * V4 + lane);
    float4 r0 = __ldg(R4 + rel.x * V4 + lane);
    float4 a1 = __ldg(X4 + src.y * V4 + lane);
    float4 b1 = __ldg(X4 + dst.y * V4 + lane);
    float4 r1 = __ldg(R4 + rel.y * V4 + lane);
    float4 a2 = __ldg(X4 + src.z * V4 + lane);
    float4 b2 = __ldg(X4 + dst.z * V4 + lane);
    float4 r2 = __ldg(R4 + rel.z * V4 + lane);

    // Edge-0 dot retires a0/b0/r0 (12 regs) ...
    float s0 = dot3(a0, r0, b0);

    // ... making room for the edge-3 gathers (MLP stays >= 6).
    float4 a3 = __ldg(X4 + src.w * V4 + lane);
    float4 b3 = __ldg(X4 + dst.w * V4 + lane);
    float4 r3 = __ldg(R4 + rel.w * V4 + lane);

    float s1 = dot3(a1, r1, b1);
    float s2 = dot3(a2, r2, b2);
    float s3 = dot3(a3, r3, b3);

    // ── Folded reduction, strictly after all loads: 8 SHFLs for 4 edges.
    s0 += __shfl_xor_sync(0xFFFFFFFFu, s0, 8);
    s1 += __shfl_xor_sync(0xFFFFFFFFu, s1, 8);
    s2 += __shfl_xor_sync(0xFFFFFFFFu, s2, 8);
    s3 += __shfl_xor_sync(0xFFFFFFFFu, s3, 8);
    float a = (lane & 8) ? s1 : s0;   // edge0 in lanes 0-7, edge1 in 8-15
    float b = (lane & 8) ? s3 : s2;   // edge2 in lanes 0-7, edge3 in 8-15
    a += __shfl_xor_sync(0xFFFFFFFFu, a, 4);
    b += __shfl_xor_sync(0xFFFFFFFFu, b, 4);
    float c = (lane & 4) ? b : a;
    // quads: lanes0-3 -> edge0, 4-7 -> edge2, 8-11 -> edge1, 12-15 -> edge3
    c += __shfl_xor_sync(0xFFFFFFFFu, c, 2);
    c += __shfl_xor_sync(0xFFFFFFFFu, c, 1);

    // lane0 -> e0+0, lane4 -> e0+2, lane8 -> e0+1, lane12 -> e0+3
    if ((lane & 3) == 0) {
        int off = ((lane >> 3) & 1) | (((lane >> 2) & 1) << 1);
        int e = e0 + off;
        if (e < num_edges)
            out[e] = c;
    }
}

extern "C" void kernel_launch(void* const* d_in, const int* in_sizes, int n_in,
                              void* d_out, int out_size)
{
    const float* X  = (const float*)d_in[0];
    const float* R  = (const float*)d_in[1];
    const int* edge_list = (const int*)d_in[2];
    const int* edge_type = (const int*)d_in[3];
    float* out = (float*)d_out;

    int num_edges = in_sizes[3];

    int groups = (num_edges + EDGES_PER_GROUP - 1) / EDGES_PER_GROUP;
    long long total_threads = (long long)groups * LANES;
    int grid = (int)((total_threads + BLOCK - 1) / BLOCK);

    distmult_kernel<<<grid, BLOCK>>>(X, R, edge_list, edge_type, out, num_edges);
}